// round 1
// baseline (speedup 1.0000x reference)
#include <cuda_runtime.h>
#include <cuda_bf16.h>
#include <math.h>

// Problem constants
#define Bn   64
#define Ln   512
#define En   300
#define Pn   200
#define Mn   7
#define Dn   2800          // P * 2 * M
#define Hn   100
#define Cn   2
#define Mtot (Bn * Ln)     // 32768
#define NEG  (-100.0f)

// Scratch (static device globals — no dynamic allocation)
__device__ float g_ts[(size_t)Mtot * Dn];     // [B*L, D]  367 MB
__device__ float g_scores[Bn * Pn];           // [B, P]

// ---------------------------------------------------------------------------
// Kernel 1: ts[m, d] = sum_k embeddings[docs[m], k] * diags[d, k] + bias[d]
// 128x128x8 double-buffered fp32 GEMM with gathered A rows.
// ---------------------------------------------------------------------------
#define BM 128
#define BN 128
#define BK 8
#define KT ((En + BK - 1) / BK)   // 38 (last tile has 4 valid k)

__global__ __launch_bounds__(256, 2)
void gemm_ts_kernel(const int* __restrict__ docs,
                    const float* __restrict__ emb,
                    const float* __restrict__ diags,
                    const float* __restrict__ bias)
{
    __shared__ float As[2][BK][BM];
    __shared__ float Bs[2][BK][BN];
    __shared__ int   toks[BM];

    const int tid = threadIdx.x;
    const int bm  = blockIdx.y * BM;
    const int bn  = blockIdx.x * BN;

    if (tid < BM) toks[tid] = docs[bm + tid];
    __syncthreads();

    const int am  = tid >> 1;          // 0..127
    const int kg  = (tid & 1) * 4;     // 0 or 4
    const int nrow = bn + am;          // diags row for B-load
    const bool nrow_ok = (nrow < Dn);

    float4 av, bv;

    // global load of k-tile kt into registers
    auto gload = [&](int kt) {
        const int k0 = kt * BK;
        const bool k_ok = (k0 + kg + 3 < En);   // all-or-none at float4 granularity
        av = make_float4(0.f, 0.f, 0.f, 0.f);
        bv = make_float4(0.f, 0.f, 0.f, 0.f);
        if (k_ok) {
            av = *reinterpret_cast<const float4*>(emb + (size_t)toks[am] * En + k0 + kg);
            if (nrow_ok)
                bv = *reinterpret_cast<const float4*>(diags + (size_t)nrow * En + k0 + kg);
        }
    };
    auto sstore = [&](int buf) {
        As[buf][kg + 0][am] = av.x;  As[buf][kg + 1][am] = av.y;
        As[buf][kg + 2][am] = av.z;  As[buf][kg + 3][am] = av.w;
        Bs[buf][kg + 0][am] = bv.x;  Bs[buf][kg + 1][am] = bv.y;
        Bs[buf][kg + 2][am] = bv.z;  Bs[buf][kg + 3][am] = bv.w;
    };

    const int tx = tid & 15;   // n-tile
    const int ty = tid >> 4;   // m-tile

    float c[8][8];
    #pragma unroll
    for (int i = 0; i < 8; i++)
        #pragma unroll
        for (int j = 0; j < 8; j++) c[i][j] = 0.f;

    gload(0);
    sstore(0);
    __syncthreads();

    int cur = 0;
    for (int kt = 0; kt < KT; kt++) {
        const bool more = (kt + 1 < KT);
        if (more) gload(kt + 1);

        #pragma unroll
        for (int kk = 0; kk < BK; kk++) {
            float4 a0 = *reinterpret_cast<const float4*>(&As[cur][kk][ty * 8]);
            float4 a1 = *reinterpret_cast<const float4*>(&As[cur][kk][ty * 8 + 4]);
            float4 b0 = *reinterpret_cast<const float4*>(&Bs[cur][kk][tx * 8]);
            float4 b1 = *reinterpret_cast<const float4*>(&Bs[cur][kk][tx * 8 + 4]);
            float ar[8] = {a0.x, a0.y, a0.z, a0.w, a1.x, a1.y, a1.z, a1.w};
            float br[8] = {b0.x, b0.y, b0.z, b0.w, b1.x, b1.y, b1.z, b1.w};
            #pragma unroll
            for (int i = 0; i < 8; i++)
                #pragma unroll
                for (int j = 0; j < 8; j++)
                    c[i][j] = fmaf(ar[i], br[j], c[i][j]);
        }

        if (more) {
            sstore(cur ^ 1);
            __syncthreads();
            cur ^= 1;
        }
    }

    // epilogue: add bias, write ts
    #pragma unroll
    for (int i = 0; i < 8; i++) {
        const int m = bm + ty * 8 + i;
        float* row = g_ts + (size_t)m * Dn;
        #pragma unroll
        for (int jv = 0; jv < 8; jv += 4) {
            const int n = bn + tx * 8 + jv;
            if (n < Dn) {
                float4 bb = *reinterpret_cast<const float4*>(bias + n);
                float4 o  = make_float4(c[i][jv + 0] + bb.x,
                                        c[i][jv + 1] + bb.y,
                                        c[i][jv + 2] + bb.z,
                                        c[i][jv + 3] + bb.w);
                *reinterpret_cast<float4*>(row + n) = o;
            }
        }
    }
}

// ---------------------------------------------------------------------------
// Kernel 2: max-plus scan over L. One thread per (b, p) chain.
// ---------------------------------------------------------------------------
__global__ void scan_kernel(const float* __restrict__ epsilon)
{
    const int id = blockIdx.x * blockDim.x + threadIdx.x;
    if (id >= Bn * Pn) return;
    const int b = id / Pn;
    const int p = id % Pn;

    float e[6];
    #pragma unroll
    for (int j = 0; j < 6; j++) e[j] = epsilon[p * 6 + j];

    float h[7];
    h[0] = 0.f;
    #pragma unroll
    for (int m = 1; m < 7; m++) h[m] = NEG;
    float s = NEG;

    const float* base = g_ts + (size_t)b * Ln * Dn + p * 14;

    for (int l = 0; l < Ln; l += 4) {
        float2 d[4][7];
        #pragma unroll
        for (int u = 0; u < 4; u++) {
            const float* x = base + (size_t)(l + u) * Dn;
            #pragma unroll
            for (int j = 0; j < 7; j++)
                d[u][j] = *reinterpret_cast<const float2*>(x + j * 2);
        }
        #pragma unroll
        for (int u = 0; u < 4; u++) {
            float xv[14];
            #pragma unroll
            for (int j = 0; j < 7; j++) { xv[2*j] = d[u][j].x; xv[2*j+1] = d[u][j].y; }
            // after_eps
            float ae[7];
            ae[0] = fmaxf(h[0], NEG);
            #pragma unroll
            for (int m = 1; m < 7; m++) ae[m] = fmaxf(h[m], h[m-1] + e[m-1]);
            // h_new = max(main, self_loop)
            float nh[7];
            nh[0] = fmaxf(0.f, ae[0] + xv[0]);
            #pragma unroll
            for (int m = 1; m < 7; m++)
                nh[m] = fmaxf(ae[m-1] + xv[7 + (m-1)], ae[m] + xv[m]);
            s = fmaxf(s, nh[6]);
            #pragma unroll
            for (int m = 0; m < 7; m++) h[m] = nh[m];
        }
    }
    g_scores[b * Pn + p] = s;
}

// ---------------------------------------------------------------------------
// Kernel 3: MLP + log_softmax. One block per batch row.
// ---------------------------------------------------------------------------
__global__ void mlp_kernel(const float* __restrict__ w1, const float* __restrict__ b1,
                           const float* __restrict__ w2, const float* __restrict__ b2,
                           const float* __restrict__ w3, const float* __restrict__ b3,
                           float* __restrict__ out)
{
    const int b = blockIdx.x;
    const int tid = threadIdx.x;
    __shared__ float sc[Pn];
    __shared__ float h1[Hn];
    __shared__ float h2[Hn];

    for (int i = tid; i < Pn; i += blockDim.x) sc[i] = g_scores[b * Pn + i];
    __syncthreads();

    if (tid < Hn) {
        float acc = b1[tid];
        #pragma unroll 4
        for (int p = 0; p < Pn; p++) acc = fmaf(sc[p], w1[p * Hn + tid], acc);
        h1[tid] = fmaxf(acc, 0.f);
    }
    __syncthreads();

    if (tid < Hn) {
        float acc = b2[tid];
        #pragma unroll 4
        for (int j = 0; j < Hn; j++) acc = fmaf(h1[j], w2[j * Hn + tid], acc);
        h2[tid] = fmaxf(acc, 0.f);
    }
    __syncthreads();

    if (tid == 0) {
        float l0 = b3[0], l1 = b3[1];
        for (int j = 0; j < Hn; j++) {
            l0 = fmaf(h2[j], w3[j * 2 + 0], l0);
            l1 = fmaf(h2[j], w3[j * 2 + 1], l1);
        }
        float mx  = fmaxf(l0, l1);
        float lse = mx + logf(expf(l0 - mx) + expf(l1 - mx));
        out[b * 2 + 0] = l0 - lse;
        out[b * 2 + 1] = l1 - lse;
    }
}

// ---------------------------------------------------------------------------
extern "C" void kernel_launch(void* const* d_in, const int* in_sizes, int n_in,
                              void* d_out, int out_size)
{
    const int*   docs    = (const int*)  d_in[0];
    const float* emb     = (const float*)d_in[1];
    const float* diags   = (const float*)d_in[2];
    const float* bias    = (const float*)d_in[3];
    const float* epsilon = (const float*)d_in[4];
    const float* w1      = (const float*)d_in[5];
    const float* b1      = (const float*)d_in[6];
    const float* w2      = (const float*)d_in[7];
    const float* b2      = (const float*)d_in[8];
    const float* w3      = (const float*)d_in[9];
    const float* b3      = (const float*)d_in[10];
    float* out = (float*)d_out;

    dim3 gridG((Dn + BN - 1) / BN, Mtot / BM);   // (22, 256)
    gemm_ts_kernel<<<gridG, 256>>>(docs, emb, diags, bias);

    scan_kernel<<<(Bn * Pn + 127) / 128, 128>>>(epsilon);

    mlp_kernel<<<Bn, 128>>>(w1, b1, w2, b2, w3, b3, out);
}

// round 4
// speedup vs baseline: 2.0912x; 2.0912x over previous
#include <cuda_runtime.h>
#include <cuda_bf16.h>
#include <math.h>
#include <stdint.h>

// Problem constants
#define Bn   64
#define Ln   512
#define En   300
#define Pn   200
#define Dn   2800          // P * 2 * M
#define Hn   100
#define Mtot (Bn * Ln)     // 32768
#define NEG  (-100.0f)

// GEMM config: K' = 3*320 (hi|hi|lo vs hi|lo|hi), N padded to 2816
#define Kp    320
#define K3    960
#define Np    2816
#define TM    128
#define TN    128
#define BK    32                 // bf16 per k-tile
#define NKT   (K3 / BK)          // 30
#define ROWB  80u                // padded smem row stride (bytes) per 32-bf16 row
#define ASZ   (128u * ROWB)      // 10240
#define STAGE (2u * ASZ)         // A + B = 20480
#define NSTG  4
#define SMEM_DYN (NSTG * STAGE)  // 81920

// Scratch (static device globals — no dynamic allocation)
__device__ float                        g_scores[Bn * Pn];
__device__ __align__(256) float         g_ts2[(size_t)Bn * Pn * Ln * 16]; // scan layout
__device__ __align__(256) __nv_bfloat16 g_A2[(size_t)Mtot * K3];
__device__ __align__(256) __nv_bfloat16 g_B2[(size_t)Np * K3];

// ---------------------------------------------------------------------------
// PTX helpers (baseline PTX only — no 'a'-target instructions)
// ---------------------------------------------------------------------------
__device__ __forceinline__ uint32_t s2u(const void* p) {
    uint32_t a;
    asm("{ .reg .u64 t; cvta.to.shared.u64 t, %1; cvt.u32.u64 %0, t; }"
        : "=r"(a) : "l"(p));
    return a;
}

#define CP_ASYNC16(dst, src) \
    asm volatile("cp.async.cg.shared.global [%0], [%1], 16;" :: "r"(dst), "l"(src) : "memory")
#define CP_COMMIT() asm volatile("cp.async.commit_group;" ::: "memory")
#define CP_WAIT(n)  asm volatile("cp.async.wait_group %0;" :: "n"(n) : "memory")

#define LDSM_X4(r, addr)                                                        \
    asm volatile("ldmatrix.sync.aligned.m8n8.x4.shared.b16 {%0,%1,%2,%3}, [%4];" \
        : "=r"((r)[0]), "=r"((r)[1]), "=r"((r)[2]), "=r"((r)[3]) : "r"(addr))

// non-trans x4 with named outputs (for B fragments)
#define LDSM_X4_B(r0, r1, r2, r3, addr)                                         \
    asm volatile("ldmatrix.sync.aligned.m8n8.x4.shared.b16 {%0,%1,%2,%3}, [%4];" \
        : "=r"(r0), "=r"(r1), "=r"(r2), "=r"(r3) : "r"(addr))

#define MMA_BF16(d, a, b)                                                       \
    asm volatile("mma.sync.aligned.m16n8k16.row.col.f32.bf16.bf16.f32 "         \
        "{%0,%1,%2,%3}, {%4,%5,%6,%7}, {%8,%9}, {%0,%1,%2,%3};"                 \
        : "+f"((d)[0]), "+f"((d)[1]), "+f"((d)[2]), "+f"((d)[3])                \
        : "r"((a)[0]), "r"((a)[1]), "r"((a)[2]), "r"((a)[3]),                   \
          "r"((b)[0]), "r"((b)[1]))

// ---------------------------------------------------------------------------
// Conversion: fp32 -> bf16 hi/lo, A gathered via docs; K padded 300->320
// A2 row = [hi(320) | hi(320) | lo(320)],  B2 row = [hi | lo | hi]
// ---------------------------------------------------------------------------
__global__ void conv_emb_kernel(const int* __restrict__ docs,
                                const float* __restrict__ emb)
{
    const int m = blockIdx.x;
    const int k = threadIdx.x;          // 0..319
    const int doc = docs[m];
    float x = (k < En) ? emb[(size_t)doc * En + k] : 0.0f;
    __nv_bfloat16 hi = __float2bfloat16(x);
    __nv_bfloat16 lo = __float2bfloat16(x - __bfloat162float(hi));
    __nv_bfloat16* row = g_A2 + (size_t)m * K3;
    row[k] = hi;  row[Kp + k] = hi;  row[2 * Kp + k] = lo;
}

__global__ void conv_diag_kernel(const float* __restrict__ diags)
{
    const int d = blockIdx.x;           // 0..2815
    const int k = threadIdx.x;
    float x = (d < Dn && k < En) ? diags[(size_t)d * En + k] : 0.0f;
    __nv_bfloat16 hi = __float2bfloat16(x);
    __nv_bfloat16 lo = __float2bfloat16(x - __bfloat162float(hi));
    __nv_bfloat16* row = g_B2 + (size_t)d * K3;
    row[k] = hi;  row[Kp + k] = lo;  row[2 * Kp + k] = hi;
}

// ---------------------------------------------------------------------------
// Kernel 1: bf16 HMMA GEMM, C[m,n] = A2[m,:]·B2[n,:] + bias[n]
// 128x128 tile, BK=32, 4-stage cp.async, warp tile 32x64 (4x2 warp grid).
// Epilogue writes directly into scan layout [B][P][L][16].
// ---------------------------------------------------------------------------
__global__ void __launch_bounds__(256)
gemm_hmma_kernel(const float* __restrict__ bias)
{
    extern __shared__ char smem[];
    const uint32_t sbase = s2u(smem);

    const int tid  = threadIdx.x;
    const int wid  = tid >> 5;
    const int lane = tid & 31;
    const int wm   = wid & 3;            // 0..3  (M)
    const int wn   = wid >> 2;           // 0..1  (N)
    const int m0   = blockIdx.y * TM;
    const int n0   = blockIdx.x * TN;

    // per-thread ldmatrix offsets (bytes within a stage)
    // A: m0..7|k0, m8..15|k0, m0..7|k8, m8..15|k8
    const uint32_t aoff = (uint32_t)((((lane >> 3) & 1) * 8 + (lane & 7)) * ROWB
                                     + ((lane >> 4) * 8) * 2);
    // B: n0..7|k0, n0..7|k8, n8..15|k0, n8..15|k8  (non-trans fragments)
    const uint32_t boff = (uint32_t)(((lane >> 4) * 8 + (lane & 7)) * ROWB
                                     + (((lane >> 3) & 1) * 8) * 2);

    // cp.async per-thread assignment: 512 chunks A + 512 chunks B per stage
    const int cr0 = tid >> 2;            // rows 0..63 for t=0, +64 for t=1
    const int cc  = (tid & 3) * 8;       // bf16 col offset (0,8,16,24)

    auto load_stage = [&](int buf, int kt) {
        const uint32_t sb = sbase + (uint32_t)buf * STAGE;
        const int kb = kt * BK;
        #pragma unroll
        for (int t = 0; t < 2; t++) {
            const int r = cr0 + t * 64;
            CP_ASYNC16(sb + (uint32_t)r * ROWB + (uint32_t)(cc * 2),
                       g_A2 + (size_t)(m0 + r) * K3 + kb + cc);
        }
        #pragma unroll
        for (int t = 0; t < 2; t++) {
            const int r = cr0 + t * 64;
            CP_ASYNC16(sb + ASZ + (uint32_t)r * ROWB + (uint32_t)(cc * 2),
                       g_B2 + (size_t)(n0 + r) * K3 + kb + cc);
        }
        CP_COMMIT();
    };

    float c[2][8][4];
    #pragma unroll
    for (int i = 0; i < 2; i++)
        #pragma unroll
        for (int j = 0; j < 8; j++)
            #pragma unroll
            for (int q = 0; q < 4; q++) c[i][j][q] = 0.f;

    load_stage(0, 0);
    load_stage(1, 1);
    load_stage(2, 2);

    for (int kt = 0; kt < NKT; kt++) {
        // taper the tail: ensure the tile we are about to consume has landed
        if      (kt <= NKT - 3) CP_WAIT(2);
        else if (kt == NKT - 2) CP_WAIT(1);
        else                    CP_WAIT(0);
        __syncthreads();

        if (kt + 3 < NKT) load_stage((kt + 3) & 3, kt + 3);

        const uint32_t sA = sbase + (uint32_t)(kt & 3) * STAGE;
        const uint32_t sB = sA + ASZ;
        #pragma unroll
        for (int ks = 0; ks < 2; ks++) {
            uint32_t a[2][4], bfr[8][2];
            #pragma unroll
            for (int i = 0; i < 2; i++)
                LDSM_X4(a[i], sA + (uint32_t)((wm * 32 + i * 16) * ROWB) + (uint32_t)(ks * 32) + aoff);
            #pragma unroll
            for (int j2 = 0; j2 < 4; j2++)
                LDSM_X4_B(bfr[j2 * 2][0], bfr[j2 * 2][1],
                          bfr[j2 * 2 + 1][0], bfr[j2 * 2 + 1][1],
                          sB + (uint32_t)((wn * 64 + j2 * 16) * ROWB) + (uint32_t)(ks * 32) + boff);
            #pragma unroll
            for (int i = 0; i < 2; i++)
                #pragma unroll
                for (int j = 0; j < 8; j++)
                    MMA_BF16(c[i][j], a[i], bfr[j]);
        }
        __syncthreads();
    }

    // ---- epilogue: write into scan layout [B][P][L][16] ----
    const int gid = lane >> 2;
    const int tig = lane & 3;
    #pragma unroll
    for (int i = 0; i < 2; i++) {
        const int mr = m0 + wm * 32 + i * 16 + gid;   // + {0,8}
        #pragma unroll
        for (int j = 0; j < 8; j++) {
            const int n  = n0 + wn * 64 + j * 8 + tig * 2;
            const int p  = n / 14;
            const int jj = n - p * 14;                // even, pair stays within p
            if (p < Pn) {
                const float bx = __ldg(bias + n);
                const float by = __ldg(bias + n + 1);
                #pragma unroll
                for (int h = 0; h < 2; h++) {
                    const int m = mr + h * 8;
                    const int b = m >> 9, l = m & 511;
                    float* dst = g_ts2 + (((size_t)(b * Pn + p) * Ln + l) << 4) + jj;
                    float2 v = make_float2(c[i][j][h * 2] + bx, c[i][j][h * 2 + 1] + by);
                    *reinterpret_cast<float2*>(dst) = v;
                }
            }
        }
    }
}

// ---------------------------------------------------------------------------
// Kernel 2: max-plus scan over L. One thread per (b, p); contiguous stream
// in scan layout with software prefetch (distance 1 group of 4 rows).
// ---------------------------------------------------------------------------
__global__ void scan_kernel(const float* __restrict__ epsilon)
{
    const int id = blockIdx.x * blockDim.x + threadIdx.x;
    if (id >= Bn * Pn) return;
    const int b = id / Pn;
    const int p = id % Pn;

    float e[6];
    #pragma unroll
    for (int j = 0; j < 6; j++) e[j] = epsilon[p * 6 + j];

    float h[7];
    h[0] = 0.f;
    #pragma unroll
    for (int m = 1; m < 7; m++) h[m] = NEG;
    float s = NEG;

    const float4* base = reinterpret_cast<const float4*>(
        g_ts2 + (((size_t)(b * Pn + p) * Ln) << 4));

    float4 nx[4][4];
    #pragma unroll
    for (int u = 0; u < 4; u++)
        #pragma unroll
        for (int q = 0; q < 4; q++) nx[u][q] = base[u * 4 + q];

    for (int l = 0; l < Ln; l += 4) {
        float4 cur[4][4];
        #pragma unroll
        for (int u = 0; u < 4; u++)
            #pragma unroll
            for (int q = 0; q < 4; q++) cur[u][q] = nx[u][q];

        if (l + 4 < Ln) {
            const float4* nb = base + (size_t)(l + 4) * 4;
            #pragma unroll
            for (int u = 0; u < 4; u++)
                #pragma unroll
                for (int q = 0; q < 4; q++) nx[u][q] = nb[u * 4 + q];
        }

        #pragma unroll
        for (int u = 0; u < 4; u++) {
            float xv[14];
            xv[0] = cur[u][0].x;  xv[1] = cur[u][0].y;  xv[2] = cur[u][0].z;  xv[3] = cur[u][0].w;
            xv[4] = cur[u][1].x;  xv[5] = cur[u][1].y;  xv[6] = cur[u][1].z;  xv[7] = cur[u][1].w;
            xv[8] = cur[u][2].x;  xv[9] = cur[u][2].y;  xv[10] = cur[u][2].z; xv[11] = cur[u][2].w;
            xv[12] = cur[u][3].x; xv[13] = cur[u][3].y;

            float ae[7];
            ae[0] = h[0];
            #pragma unroll
            for (int m = 1; m < 7; m++) ae[m] = fmaxf(h[m], h[m - 1] + e[m - 1]);
            float nh[7];
            nh[0] = fmaxf(0.f, ae[0] + xv[0]);
            #pragma unroll
            for (int m = 1; m < 7; m++)
                nh[m] = fmaxf(ae[m - 1] + xv[7 + (m - 1)], ae[m] + xv[m]);
            s = fmaxf(s, nh[6]);
            #pragma unroll
            for (int m = 0; m < 7; m++) h[m] = nh[m];
        }
    }
    g_scores[b * Pn + p] = s;
}

// ---------------------------------------------------------------------------
// Kernel 3: MLP + log_softmax. One block per batch row.
// ---------------------------------------------------------------------------
__global__ void mlp_kernel(const float* __restrict__ w1, const float* __restrict__ b1,
                           const float* __restrict__ w2, const float* __restrict__ b2,
                           const float* __restrict__ w3, const float* __restrict__ b3,
                           float* __restrict__ out)
{
    const int b = blockIdx.x;
    const int tid = threadIdx.x;
    __shared__ float sc[Pn];
    __shared__ float h1[Hn];
    __shared__ float h2[Hn];

    for (int i = tid; i < Pn; i += blockDim.x) sc[i] = g_scores[b * Pn + i];
    __syncthreads();

    if (tid < Hn) {
        float acc = b1[tid];
        #pragma unroll 4
        for (int p = 0; p < Pn; p++) acc = fmaf(sc[p], w1[p * Hn + tid], acc);
        h1[tid] = fmaxf(acc, 0.f);
    }
    __syncthreads();

    if (tid < Hn) {
        float acc = b2[tid];
        #pragma unroll 4
        for (int j = 0; j < Hn; j++) acc = fmaf(h1[j], w2[j * Hn + tid], acc);
        h2[tid] = fmaxf(acc, 0.f);
    }
    __syncthreads();

    if (tid == 0) {
        float l0 = b3[0], l1 = b3[1];
        for (int j = 0; j < Hn; j++) {
            l0 = fmaf(h2[j], w3[j * 2 + 0], l0);
            l1 = fmaf(h2[j], w3[j * 2 + 1], l1);
        }
        float mx  = fmaxf(l0, l1);
        float lse = mx + logf(expf(l0 - mx) + expf(l1 - mx));
        out[b * 2 + 0] = l0 - lse;
        out[b * 2 + 1] = l1 - lse;
    }
}

// ---------------------------------------------------------------------------
extern "C" void kernel_launch(void* const* d_in, const int* in_sizes, int n_in,
                              void* d_out, int out_size)
{
    const int*   docs    = (const int*)  d_in[0];
    const float* emb     = (const float*)d_in[1];
    const float* diags   = (const float*)d_in[2];
    const float* bias    = (const float*)d_in[3];
    const float* epsilon = (const float*)d_in[4];
    const float* w1      = (const float*)d_in[5];
    const float* b1      = (const float*)d_in[6];
    const float* w2      = (const float*)d_in[7];
    const float* b2      = (const float*)d_in[8];
    const float* w3      = (const float*)d_in[9];
    const float* b3      = (const float*)d_in[10];
    float* out = (float*)d_out;

    cudaFuncSetAttribute(gemm_hmma_kernel,
                         cudaFuncAttributeMaxDynamicSharedMemorySize, SMEM_DYN);

    conv_emb_kernel<<<Mtot, Kp>>>(docs, emb);
    conv_diag_kernel<<<Np, Kp>>>(diags);

    dim3 gridG(Np / TN, Mtot / TM);   // (22, 256)
    gemm_hmma_kernel<<<gridG, 256, SMEM_DYN>>>(bias);

    scan_kernel<<<(Bn * Pn + 127) / 128, 128>>>(epsilon);

    mlp_kernel<<<Bn, 128>>>(w1, b1, w2, b2, w3, b3, out);
}

// round 5
// speedup vs baseline: 2.1925x; 1.0484x over previous
#include <cuda_runtime.h>
#include <cuda_bf16.h>
#include <math.h>
#include <stdint.h>

// Problem constants
#define Bn   64
#define Ln   512
#define En   300
#define Pn   200
#define Dn   2800          // P * 2 * M
#define Hn   100
#define Mtot (Bn * Ln)     // 32768
#define NEG  (-100.0f)
#define NINF (-1.0e30f)

// GEMM config: K' = 3*320 (hi|hi|lo vs hi|lo|hi), N padded to 2816
#define Kp    320
#define K3    960
#define Np    2816
#define TM    128
#define TN    128
#define BK    32                 // bf16 per k-tile
#define NKT   (K3 / BK)          // 30
#define ROWB  80u                // padded smem row stride (bytes) per 32-bf16 row
#define ASZ   (128u * ROWB)      // 10240
#define STAGE (2u * ASZ)         // A + B = 20480
#define NSTG  3
#define SMEM_DYN (NSTG * STAGE)  // 61440

// Scan split config
#define NCH  4
#define CL   (Ln / NCH)          // 128

// Scratch (static device globals — no dynamic allocation)
__device__ float                        g_scores[Bn * Pn];
__device__ __align__(256) float         g_ts2[(size_t)Bn * Pn * Ln * 16]; // scan layout
__device__ __align__(256) float         g_part[(size_t)Bn * Pn * NCH * 64];
__device__ __align__(256) __nv_bfloat16 g_A2[(size_t)Mtot * K3];
__device__ __align__(256) __nv_bfloat16 g_B2[(size_t)Np * K3];

// ---------------------------------------------------------------------------
// PTX helpers (baseline PTX only — no 'a'-target instructions)
// ---------------------------------------------------------------------------
__device__ __forceinline__ uint32_t s2u(const void* p) {
    uint32_t a;
    asm("{ .reg .u64 t; cvta.to.shared.u64 t, %1; cvt.u32.u64 %0, t; }"
        : "=r"(a) : "l"(p));
    return a;
}

#define CP_ASYNC16(dst, src) \
    asm volatile("cp.async.cg.shared.global [%0], [%1], 16;" :: "r"(dst), "l"(src) : "memory")
#define CP_COMMIT() asm volatile("cp.async.commit_group;" ::: "memory")
#define CP_WAIT(n)  asm volatile("cp.async.wait_group %0;" :: "n"(n) : "memory")

#define LDSM_X4(r, addr)                                                        \
    asm volatile("ldmatrix.sync.aligned.m8n8.x4.shared.b16 {%0,%1,%2,%3}, [%4];" \
        : "=r"((r)[0]), "=r"((r)[1]), "=r"((r)[2]), "=r"((r)[3]) : "r"(addr))

#define LDSM_X4_B(r0, r1, r2, r3, addr)                                         \
    asm volatile("ldmatrix.sync.aligned.m8n8.x4.shared.b16 {%0,%1,%2,%3}, [%4];" \
        : "=r"(r0), "=r"(r1), "=r"(r2), "=r"(r3) : "r"(addr))

#define MMA_BF16(d, a, b)                                                       \
    asm volatile("mma.sync.aligned.m16n8k16.row.col.f32.bf16.bf16.f32 "         \
        "{%0,%1,%2,%3}, {%4,%5,%6,%7}, {%8,%9}, {%0,%1,%2,%3};"                 \
        : "+f"((d)[0]), "+f"((d)[1]), "+f"((d)[2]), "+f"((d)[3])                \
        : "r"((a)[0]), "r"((a)[1]), "r"((a)[2]), "r"((a)[3]),                   \
          "r"((b)[0]), "r"((b)[1]))

// ---------------------------------------------------------------------------
// Conversion: fp32 -> bf16 hi/lo, A gathered via docs; K padded 300->320
// A2 row = [hi(320) | hi(320) | lo(320)],  B2 row = [hi | lo | hi]
// ---------------------------------------------------------------------------
__global__ void conv_emb_kernel(const int* __restrict__ docs,
                                const float* __restrict__ emb)
{
    const int m = blockIdx.x;
    const int k = threadIdx.x;          // 0..319
    const int doc = docs[m];
    float x = (k < En) ? emb[(size_t)doc * En + k] : 0.0f;
    __nv_bfloat16 hi = __float2bfloat16(x);
    __nv_bfloat16 lo = __float2bfloat16(x - __bfloat162float(hi));
    __nv_bfloat16* row = g_A2 + (size_t)m * K3;
    row[k] = hi;  row[Kp + k] = hi;  row[2 * Kp + k] = lo;
}

__global__ void conv_diag_kernel(const float* __restrict__ diags)
{
    const int d = blockIdx.x;           // 0..2815
    const int k = threadIdx.x;
    float x = (d < Dn && k < En) ? diags[(size_t)d * En + k] : 0.0f;
    __nv_bfloat16 hi = __float2bfloat16(x);
    __nv_bfloat16 lo = __float2bfloat16(x - __bfloat162float(hi));
    __nv_bfloat16* row = g_B2 + (size_t)d * K3;
    row[k] = hi;  row[Kp + k] = lo;  row[2 * Kp + k] = hi;
}

// ---------------------------------------------------------------------------
// Kernel 1: bf16 HMMA GEMM, C[m,n] = A2[m,:]·B2[n,:] + bias[n]
// 128x128 tile, BK=32, 3-stage cp.async, warp tile 32x64, 2 CTAs/SM.
// Epilogue writes directly into scan layout [B][P][L][16].
// ---------------------------------------------------------------------------
__global__ void __launch_bounds__(256, 2)
gemm_hmma_kernel(const float* __restrict__ bias)
{
    extern __shared__ char smem[];
    const uint32_t sbase = s2u(smem);

    const int tid  = threadIdx.x;
    const int wid  = tid >> 5;
    const int lane = tid & 31;
    const int wm   = wid & 3;            // 0..3  (M)
    const int wn   = wid >> 2;           // 0..1  (N)
    const int m0   = blockIdx.y * TM;
    const int n0   = blockIdx.x * TN;

    // per-thread ldmatrix offsets (bytes within a stage)
    const uint32_t aoff = (uint32_t)((((lane >> 3) & 1) * 8 + (lane & 7)) * ROWB
                                     + ((lane >> 4) * 8) * 2);
    const uint32_t boff = (uint32_t)(((lane >> 4) * 8 + (lane & 7)) * ROWB
                                     + (((lane >> 3) & 1) * 8) * 2);

    const int cr0 = tid >> 2;            // rows 0..63 for t=0, +64 for t=1
    const int cc  = (tid & 3) * 8;       // bf16 col offset (0,8,16,24)

    auto load_stage = [&](int buf, int kt) {
        const uint32_t sb = sbase + (uint32_t)buf * STAGE;
        const int kb = kt * BK;
        #pragma unroll
        for (int t = 0; t < 2; t++) {
            const int r = cr0 + t * 64;
            CP_ASYNC16(sb + (uint32_t)r * ROWB + (uint32_t)(cc * 2),
                       g_A2 + (size_t)(m0 + r) * K3 + kb + cc);
        }
        #pragma unroll
        for (int t = 0; t < 2; t++) {
            const int r = cr0 + t * 64;
            CP_ASYNC16(sb + ASZ + (uint32_t)r * ROWB + (uint32_t)(cc * 2),
                       g_B2 + (size_t)(n0 + r) * K3 + kb + cc);
        }
        CP_COMMIT();
    };

    float c[2][8][4];
    #pragma unroll
    for (int i = 0; i < 2; i++)
        #pragma unroll
        for (int j = 0; j < 8; j++)
            #pragma unroll
            for (int q = 0; q < 4; q++) c[i][j][q] = 0.f;

    load_stage(0, 0);
    load_stage(1, 1);

    for (int kt = 0; kt < NKT; kt++) {
        if (kt < NKT - 1) CP_WAIT(1);
        else              CP_WAIT(0);
        __syncthreads();   // all reads of buffer (kt-1)%3 complete before overwrite

        if (kt + 2 < NKT) load_stage((kt + 2) % NSTG, kt + 2);

        const uint32_t sA = sbase + (uint32_t)(kt % NSTG) * STAGE;
        const uint32_t sB = sA + ASZ;
        #pragma unroll
        for (int ks = 0; ks < 2; ks++) {
            uint32_t a[2][4], bfr[8][2];
            #pragma unroll
            for (int i = 0; i < 2; i++)
                LDSM_X4(a[i], sA + (uint32_t)((wm * 32 + i * 16) * ROWB) + (uint32_t)(ks * 32) + aoff);
            #pragma unroll
            for (int j2 = 0; j2 < 4; j2++)
                LDSM_X4_B(bfr[j2 * 2][0], bfr[j2 * 2][1],
                          bfr[j2 * 2 + 1][0], bfr[j2 * 2 + 1][1],
                          sB + (uint32_t)((wn * 64 + j2 * 16) * ROWB) + (uint32_t)(ks * 32) + boff);
            #pragma unroll
            for (int i = 0; i < 2; i++)
                #pragma unroll
                for (int j = 0; j < 8; j++)
                    MMA_BF16(c[i][j], a[i], bfr[j]);
        }
    }

    // ---- epilogue: write into scan layout [B][P][L][16] ----
    const int gid = lane >> 2;
    const int tig = lane & 3;
    #pragma unroll
    for (int i = 0; i < 2; i++) {
        const int mr = m0 + wm * 32 + i * 16 + gid;   // + {0,8}
        #pragma unroll
        for (int j = 0; j < 8; j++) {
            const int n  = n0 + wn * 64 + j * 8 + tig * 2;
            const int p  = n / 14;
            const int jj = n - p * 14;                // even, pair stays within p
            if (p < Pn) {
                const float bx = __ldg(bias + n);
                const float by = __ldg(bias + n + 1);
                #pragma unroll
                for (int h = 0; h < 2; h++) {
                    const int m = mr + h * 8;
                    const int b = m >> 9, l = m & 511;
                    float* dst = g_ts2 + (((size_t)(b * Pn + p) * Ln + l) << 4) + jj;
                    float2 v = make_float2(c[i][j][h * 2] + bx, c[i][j][h * 2 + 1] + by);
                    *reinterpret_cast<float2*>(dst) = v;
                }
            }
        }
    }
}

// ---------------------------------------------------------------------------
// Kernel 2a: chunked max-plus scan. One thread per (b,p,chunk); computes the
// chunk's max-plus affine transform: 7 basis columns (zero = -1e30, no
// restart), 1 const column (exact reference semantics incl. restart), and
// per-column running max of state 6 (the s-row).
// Slot layout (64 floats): [0..48] M cols j*7+i, [49..55] C, [56..63] S.
// ---------------------------------------------------------------------------
__global__ void __launch_bounds__(128, 4)
scan_part_kernel(const float* __restrict__ epsilon)
{
    const int id = blockIdx.x * blockDim.x + threadIdx.x;
    if (id >= Bn * Pn * NCH) return;
    const int c  = id & (NCH - 1);
    const int bp = id >> 2;
    const int p  = bp % Pn;

    float e[6];
    #pragma unroll
    for (int j = 0; j < 6; j++) e[j] = __ldg(epsilon + p * 6 + j);

    float h[8][7];
    #pragma unroll
    for (int j = 0; j < 8; j++)
        #pragma unroll
        for (int i = 0; i < 7; i++) h[j][i] = NINF;
    #pragma unroll
    for (int j = 0; j < 7; j++) h[j][j] = 0.0f;
    float smax[8];
    #pragma unroll
    for (int j = 0; j < 8; j++) smax[j] = NINF;

    const float4* base = reinterpret_cast<const float4*>(
        g_ts2 + (((size_t)bp * Ln + c * CL) << 4));

    float4 nx[2][4];
    #pragma unroll
    for (int u = 0; u < 2; u++)
        #pragma unroll
        for (int q = 0; q < 4; q++) nx[u][q] = base[u * 4 + q];

    for (int l = 0; l < CL; l += 2) {
        float4 cur[2][4];
        #pragma unroll
        for (int u = 0; u < 2; u++)
            #pragma unroll
            for (int q = 0; q < 4; q++) cur[u][q] = nx[u][q];
        if (l + 2 < CL) {
            const float4* nb = base + (size_t)(l + 2) * 4;
            #pragma unroll
            for (int u = 0; u < 2; u++)
                #pragma unroll
                for (int q = 0; q < 4; q++) nx[u][q] = nb[u * 4 + q];
        }

        #pragma unroll
        for (int u = 0; u < 2; u++) {
            float xv[14];
            xv[0]  = cur[u][0].x;  xv[1]  = cur[u][0].y;  xv[2]  = cur[u][0].z;  xv[3]  = cur[u][0].w;
            xv[4]  = cur[u][1].x;  xv[5]  = cur[u][1].y;  xv[6]  = cur[u][1].z;  xv[7]  = cur[u][1].w;
            xv[8]  = cur[u][2].x;  xv[9]  = cur[u][2].y;  xv[10] = cur[u][2].z;  xv[11] = cur[u][2].w;
            xv[12] = cur[u][3].x;  xv[13] = cur[u][3].y;

            #pragma unroll
            for (int j = 0; j < 8; j++) {
                float ae[7];
                ae[0] = (j == 7) ? fmaxf(h[j][0], NEG) : h[j][0];
                #pragma unroll
                for (int m = 1; m < 7; m++)
                    ae[m] = fmaxf(h[j][m], h[j][m - 1] + e[m - 1]);
                float nh[7];
                nh[0] = ae[0] + xv[0];
                if (j == 7) nh[0] = fmaxf(0.0f, nh[0]);
                #pragma unroll
                for (int m = 1; m < 7; m++)
                    nh[m] = fmaxf(ae[m - 1] + xv[7 + (m - 1)], ae[m] + xv[m]);
                smax[j] = fmaxf(smax[j], nh[6]);
                #pragma unroll
                for (int m = 0; m < 7; m++) h[j][m] = nh[m];
            }
        }
    }

    float* slot = g_part + (size_t)id * 64;
    #pragma unroll
    for (int j = 0; j < 7; j++)
        #pragma unroll
        for (int i = 0; i < 7; i++) slot[j * 7 + i] = h[j][i];
    #pragma unroll
    for (int i = 0; i < 7; i++) slot[49 + i] = h[7][i];
    #pragma unroll
    for (int j = 0; j < 8; j++) slot[56 + j] = smax[j];
}

// ---------------------------------------------------------------------------
// Kernel 2b: combine the 4 chunk transforms per chain.
// ---------------------------------------------------------------------------
__global__ void scan_combine_kernel()
{
    const int bp = blockIdx.x * blockDim.x + threadIdx.x;
    if (bp >= Bn * Pn) return;

    float h[7];
    h[0] = 0.0f;
    #pragma unroll
    for (int i = 1; i < 7; i++) h[i] = NEG;
    float s = NEG;

    #pragma unroll 1
    for (int c = 0; c < NCH; c++) {
        const float* sl = g_part + ((size_t)bp * NCH + c) * 64;
        float ns = fmaxf(s, sl[63]);               // const-column S
        #pragma unroll
        for (int j = 0; j < 7; j++) ns = fmaxf(ns, sl[56 + j] + h[j]);
        float nh[7];
        #pragma unroll
        for (int i = 0; i < 7; i++) {
            float v = sl[49 + i];                  // const column
            #pragma unroll
            for (int j = 0; j < 7; j++) v = fmaxf(v, sl[j * 7 + i] + h[j]);
            nh[i] = v;
        }
        #pragma unroll
        for (int i = 0; i < 7; i++) h[i] = nh[i];
        s = ns;
    }
    g_scores[bp] = s;
}

// ---------------------------------------------------------------------------
// Kernel 3: MLP + log_softmax. One block per batch row.
// ---------------------------------------------------------------------------
__global__ void mlp_kernel(const float* __restrict__ w1, const float* __restrict__ b1,
                           const float* __restrict__ w2, const float* __restrict__ b2,
                           const float* __restrict__ w3, const float* __restrict__ b3,
                           float* __restrict__ out)
{
    const int b = blockIdx.x;
    const int tid = threadIdx.x;
    __shared__ float sc[Pn];
    __shared__ float h1[Hn];
    __shared__ float h2[Hn];

    for (int i = tid; i < Pn; i += blockDim.x) sc[i] = g_scores[b * Pn + i];
    __syncthreads();

    if (tid < Hn) {
        float acc = b1[tid];
        #pragma unroll 4
        for (int p = 0; p < Pn; p++) acc = fmaf(sc[p], w1[p * Hn + tid], acc);
        h1[tid] = fmaxf(acc, 0.f);
    }
    __syncthreads();

    if (tid < Hn) {
        float acc = b2[tid];
        #pragma unroll 4
        for (int j = 0; j < Hn; j++) acc = fmaf(h1[j], w2[j * Hn + tid], acc);
        h2[tid] = fmaxf(acc, 0.f);
    }
    __syncthreads();

    if (tid == 0) {
        float l0 = b3[0], l1 = b3[1];
        for (int j = 0; j < Hn; j++) {
            l0 = fmaf(h2[j], w3[j * 2 + 0], l0);
            l1 = fmaf(h2[j], w3[j * 2 + 1], l1);
        }
        float mx  = fmaxf(l0, l1);
        float lse = mx + logf(expf(l0 - mx) + expf(l1 - mx));
        out[b * 2 + 0] = l0 - lse;
        out[b * 2 + 1] = l1 - lse;
    }
}

// ---------------------------------------------------------------------------
extern "C" void kernel_launch(void* const* d_in, const int* in_sizes, int n_in,
                              void* d_out, int out_size)
{
    const int*   docs    = (const int*)  d_in[0];
    const float* emb     = (const float*)d_in[1];
    const float* diags   = (const float*)d_in[2];
    const float* bias    = (const float*)d_in[3];
    const float* epsilon = (const float*)d_in[4];
    const float* w1      = (const float*)d_in[5];
    const float* b1      = (const float*)d_in[6];
    const float* w2      = (const float*)d_in[7];
    const float* b2      = (const float*)d_in[8];
    const float* w3      = (const float*)d_in[9];
    const float* b3      = (const float*)d_in[10];
    float* out = (float*)d_out;

    cudaFuncSetAttribute(gemm_hmma_kernel,
                         cudaFuncAttributeMaxDynamicSharedMemorySize, SMEM_DYN);

    conv_emb_kernel<<<Mtot, Kp>>>(docs, emb);
    conv_diag_kernel<<<Np, Kp>>>(diags);

    dim3 gridG(Np / TN, Mtot / TM);   // (22, 256)
    gemm_hmma_kernel<<<gridG, 256, SMEM_DYN>>>(bias);

    scan_part_kernel<<<(Bn * Pn * NCH + 127) / 128, 128>>>(epsilon);
    scan_combine_kernel<<<(Bn * Pn + 127) / 128, 128>>>();

    mlp_kernel<<<Bn, 128>>>(w1, b1, w2, b2, w3, b3, out);
}